// round 16
// baseline (speedup 1.0000x reference)
#include <cuda_runtime.h>
#include <cstdint>
#include <math.h>

#define NTOK 2048
#define HD   2048
#define NE   8
#define ID   1024
#define MAXPE 2048
#define KC   32
#define NSTAGE 3

__device__ int   g_count[NE];       // zero at load; re-zeroed by reset_kernel each call
__device__ int   g_tok[NE * MAXPE];
__device__ float g_wt [NE * MAXPE];
// packed bf16 hi/lo planes (word = bf16x2: lo16 = even element, hi16 = odd)
__device__ uint32_t g_w13h[(size_t)NE * HD * ID];        // word(e,k,n) = (gate_n, up_n)
__device__ uint32_t g_w13l[(size_t)NE * HD * ID];
__device__ uint32_t g_w2h [(size_t)NE * ID * (HD / 2)];  // word(e,k,j) = (w2[k,2j], w2[k,2j+1])
__device__ uint32_t g_w2l [(size_t)NE * ID * (HD / 2)];
__device__ uint32_t g_xh  [(size_t)NTOK * (HD / 2)];
__device__ uint32_t g_xl  [(size_t)NTOK * (HD / 2)];
__device__ uint32_t g_acth[(size_t)NE * MAXPE * (ID / 2)];
__device__ uint32_t g_actl[(size_t)NE * MAXPE * (ID / 2)];

// ---------------- helpers ----------------
__device__ __forceinline__ uint32_t smem_u32(const void* p) {
    uint32_t a;
    asm("{ .reg .u64 t; cvta.to.shared.u64 t, %1; cvt.u32.u64 %0, t; }" : "=r"(a) : "l"(p));
    return a;
}
__device__ __forceinline__ void cp16(uint32_t dst, const void* src) {
    asm volatile("cp.async.cg.shared.global [%0], [%1], 16;" :: "r"(dst), "l"(src) : "memory");
}
#define CP_COMMIT() asm volatile("cp.async.commit_group;" ::: "memory")
#define CP_WAIT1()  asm volatile("cp.async.wait_group 1;" ::: "memory")

__device__ __forceinline__ void cvt_hl(float a0, float a1, uint32_t& hi, uint32_t& lo) {
    uint32_t h;
    asm("cvt.rn.bf16x2.f32 %0, %1, %2;" : "=r"(h) : "f"(a1), "f"(a0));  // lo16=a0, hi16=a1
    float h0 = __uint_as_float(h << 16);
    float h1 = __uint_as_float(h & 0xFFFF0000u);
    uint32_t l;
    float l1 = a1 - h1, l0 = a0 - h0;
    asm("cvt.rn.bf16x2.f32 %0, %1, %2;" : "=r"(l) : "f"(l1), "f"(l0));
    hi = h; lo = l;
}
__device__ __forceinline__ void mma16816(float* c, const uint32_t* a, const uint32_t* b) {
    asm volatile("mma.sync.aligned.m16n8k16.row.col.f32.bf16.bf16.f32 "
        "{%0,%1,%2,%3}, {%4,%5,%6,%7}, {%8,%9}, {%0,%1,%2,%3};"
        : "+f"(c[0]), "+f"(c[1]), "+f"(c[2]), "+f"(c[3])
        : "r"(a[0]), "r"(a[1]), "r"(a[2]), "r"(a[3]), "r"(b[0]), "r"(b[1]));
}
__device__ __forceinline__ void ldsm4(uint32_t* r, uint32_t addr) {
    asm volatile("ldmatrix.sync.aligned.m8n8.x4.shared.b16 {%0,%1,%2,%3}, [%4];"
        : "=r"(r[0]), "=r"(r[1]), "=r"(r[2]), "=r"(r[3]) : "r"(addr));
}
__device__ __forceinline__ void ldsm4t(uint32_t* r, uint32_t addr) {
    asm volatile("ldmatrix.sync.aligned.m8n8.x4.trans.shared.b16 {%0,%1,%2,%3}, [%4];"
        : "=r"(r[0]), "=r"(r[1]), "=r"(r[2]), "=r"(r[3]) : "r"(addr));
}
// vector reduction: two adjacent f32 adds in one op (sm_90+)
__device__ __forceinline__ void red2(float* p, float a, float b) {
    asm volatile("red.global.add.v2.f32 [%0], {%1, %2};" :: "l"(p), "f"(a), "f"(b) : "memory");
}

// SMEM stage layout (identical geometry to validated R5/R8/R9/R11 kernels)
#define ASTRIDE 80
#define BSTRIDE 272
#define SZ_A (128 * ASTRIDE)
#define SZ_B (32 * BSTRIDE)
#define OFF_AH 0
#define OFF_AL SZ_A
#define OFF_BH (2 * SZ_A)
#define OFF_BL (2 * SZ_A + SZ_B)
#define STAGE_SZ (2 * SZ_A + 2 * SZ_B)     // 37888
#define SM_TOK 0
#define SM_WT  512
#define SM_STAGE 1024
#define SMEM_SZ (SM_STAGE + NSTAGE * STAGE_SZ)   // 114688 -> 2 CTAs/SM

// ---------------------------------------------------------------------------
// Fused prologue: pack13 | pack2 | init(out) | router, one launch. All four
// sections are mutually independent (router transposes gw itself in smem and
// g_count is pre-zeroed by the previous call's reset_kernel / load-time init).
// Block ranges: [0,16384) pack13, [16384,24576) pack2, [24576,28672) init,
// [28672,30720) router (block - 28672 = token id).
// ---------------------------------------------------------------------------
#define PREP_P13 16384
#define PREP_P2  (PREP_P13 + 8192)
#define PREP_INI (PREP_P2 + 4096)
#define PREP_TOT (PREP_INI + NTOK)
#define GW_PAD   1036                      // floats per e-row (1024 + 12 pad)
#define PREP_SMEM (NE * GW_PAD * 4)        // 33152 B

__global__ void prep_kernel(const float* __restrict__ w13,
                            const float* __restrict__ w2,
                            const float* __restrict__ gw,
                            const float* __restrict__ x,
                            float4* __restrict__ out4) {
    const int b = blockIdx.x, tid = threadIdx.x;
    if (b < PREP_P13) {
        size_t q = (size_t)b * 256 + tid;            // over NE*HD*ID/4
        size_t row = q / (ID / 4);
        int n = (int)(q % (ID / 4)) * 4;
        const float* base = w13 + row * (2 * ID);
        float4 gv = *(const float4*)(base + n);
        float4 uv = *(const float4*)(base + ID + n);
        uint4 h4, l4;
        cvt_hl(gv.x, uv.x, h4.x, l4.x);
        cvt_hl(gv.y, uv.y, h4.y, l4.y);
        cvt_hl(gv.z, uv.z, h4.z, l4.z);
        cvt_hl(gv.w, uv.w, h4.w, l4.w);
        size_t widx = row * ID + n;
        *(uint4*)&g_w13h[widx] = h4;
        *(uint4*)&g_w13l[widx] = l4;
    } else if (b < PREP_P2) {
        size_t q = (size_t)(b - PREP_P13) * 256 + tid;   // over NE*ID*HD/8
        const float4* src = (const float4*)w2 + q * 2;
        float4 v0 = src[0], v1 = src[1];
        uint4 h4, l4;
        cvt_hl(v0.x, v0.y, h4.x, l4.x);
        cvt_hl(v0.z, v0.w, h4.y, l4.y);
        cvt_hl(v1.x, v1.y, h4.z, l4.z);
        cvt_hl(v1.z, v1.w, h4.w, l4.w);
        *(uint4*)&g_w2h[q * 4] = h4;
        *(uint4*)&g_w2l[q * 4] = l4;
    } else if (b < PREP_INI) {
        int idx = (b - PREP_P2) * 256 + tid;             // over NTOK*HD/4
        out4[idx] = make_float4(0.f, 0.f, 0.f, 0.f);
    } else {
        // ---- router for token t, with in-block gw transpose staging ----
        extern __shared__ float sgw[];                   // [NE][GW_PAD]
        const int t = b - PREP_INI;
        float p[NE];
#pragma unroll
        for (int e = 0; e < NE; e++) p[e] = 0.f;
        const float* xr = x + (size_t)t * HD;
        const float4* gwf4 = (const float4*)gw;          // 4096 float4 total

#pragma unroll
        for (int half = 0; half < 2; half++) {
            // stage 1024 gw rows transposed: coalesced f4 loads, padded STS
#pragma unroll
            for (int i = 0; i < 8; i++) {
                int j = half * 2048 + i * 256 + tid;     // f4 index
                float4 v = gwf4[j];
                int row = (j >> 1) - half * 1024;        // 0..1023
                int eb = (j & 1) * 4;
                sgw[(eb + 0) * GW_PAD + row] = v.x;
                sgw[(eb + 1) * GW_PAD + row] = v.y;
                sgw[(eb + 2) * GW_PAD + row] = v.z;
                sgw[(eb + 3) * GW_PAD + row] = v.w;
            }
            __syncthreads();
            int h0 = half * 1024 + tid * 4;
            float4 xv = *(const float4*)(xr + h0);
            uint4 h4, l4_;
            cvt_hl(xv.x, xv.y, h4.x, l4_.x);
            cvt_hl(xv.z, xv.w, h4.y, l4_.y);
            size_t wbase = (size_t)t * (HD / 2) + h0 / 2;
            *(uint2*)&g_xh[wbase] = make_uint2(h4.x, h4.y);
            *(uint2*)&g_xl[wbase] = make_uint2(l4_.x, l4_.y);
#pragma unroll
            for (int e = 0; e < NE; e++) {
                float4 gv = *(const float4*)&sgw[e * GW_PAD + tid * 4];
                p[e] = fmaf(xv.x, gv.x, p[e]);
                p[e] = fmaf(xv.y, gv.y, p[e]);
                p[e] = fmaf(xv.z, gv.z, p[e]);
                p[e] = fmaf(xv.w, gv.w, p[e]);
            }
            __syncthreads();
        }
#pragma unroll
        for (int e = 0; e < NE; e++)
#pragma unroll
            for (int o = 16; o > 0; o >>= 1)
                p[e] += __shfl_xor_sync(0xffffffffu, p[e], o);
        float* s = sgw;                                  // reuse smem for reduce
        int warp = tid >> 5, lane = tid & 31;
        if (lane == 0)
#pragma unroll
            for (int e = 0; e < NE; e++) s[warp * NE + e] = p[e];
        __syncthreads();
        if (tid == 0) {
            float logit[NE];
#pragma unroll
            for (int e = 0; e < NE; e++) {
                float v = 0.f;
#pragma unroll
                for (int w = 0; w < 8; w++) v += s[w * NE + e];
                logit[e] = v;
            }
            int i0 = 0;
#pragma unroll
            for (int e = 1; e < NE; e++) if (logit[e] > logit[i0]) i0 = e;
            int i1 = -1;
#pragma unroll
            for (int e = 0; e < NE; e++)
                if (e != i0 && (i1 < 0 || logit[e] > logit[i1])) i1 = e;
            float pr = expf(logit[i1] - logit[i0]);
            int p0 = atomicAdd(&g_count[i0], 1);
            g_tok[i0 * MAXPE + p0] = t; g_wt[i0 * MAXPE + p0] = 1.f / (1.f + pr);
            int p1 = atomicAdd(&g_count[i1], 1);
            g_tok[i1 * MAXPE + p1] = t; g_wt[i1 * MAXPE + p1] = pr / (1.f + pr);
        }
    }
}

// Re-zero expert counters for the next invocation (runs after ffn kernels).
__global__ void reset_kernel() {
    if (threadIdx.x < NE) g_count[threadIdx.x] = 0;
}

// ---------------------------------------------------------------------------
// GEMM (R11 exact): 256 threads, 8 warps as 4M x 2N, CTA 128x128, pure
// cp.async from packed planes, 3-stage ring. bf16x3 (ah*bh, al*bh, ah*bl),
// bl loaded per-jp in pass 3 (register-pressure-optimal schedule).
// ---------------------------------------------------------------------------
template <int NCHUNK, int AW, int BW>
__device__ __forceinline__ void gemm_pk(
    const uint32_t* __restrict__ a0h, const uint32_t* __restrict__ a0l,  // row r0 = tid>>2
    const uint32_t* __restrict__ a1h, const uint32_t* __restrict__ a1l,  // row r0+64
    const uint32_t* __restrict__ bh0, const uint32_t* __restrict__ bl0,
    uint32_t sb, float c[2][8][4])
{
    const int tid = threadIdx.x;
    const int lane = tid & 31, w = tid >> 5;
    const int wm = w & 3, wn = w >> 2;
    const int lrow8 = ((lane >> 3) & 1) * 8 + (lane & 7);
    const int lk16 = (lane & 16) ? 16 : 0;
    const uint32_t a_base = (uint32_t)(wm * 32 + lrow8) * ASTRIDE + lk16;
    const uint32_t b_base = (uint32_t)lrow8 * BSTRIDE + wn * 128 + lk16;
    const int r0 = tid >> 2, seg_a = tid & 3;
    const int kb = tid >> 4, seg_b = tid & 15;

    auto issue = [&](int k0, int buf) {
        uint32_t st = sb + SM_STAGE + buf * STAGE_SZ;
        const int kw = k0 / 2;
        uint32_t ad0 = st + OFF_AH + r0 * ASTRIDE + seg_a * 16;
        uint32_t ad1 = st + OFF_AH + (r0 + 64) * ASTRIDE + seg_a * 16;
        cp16(ad0, a0h + kw + seg_a * 4);
        cp16(ad1, a1h + kw + seg_a * 4);
        cp16(ad0 + (OFF_AL - OFF_AH), a0l + kw + seg_a * 4);
        cp16(ad1 + (OFF_AL - OFF_AH), a1l + kw + seg_a * 4);
        uint32_t bd0 = st + OFF_BH + kb * BSTRIDE + seg_b * 16;
        uint32_t bd1 = st + OFF_BH + (kb + 16) * BSTRIDE + seg_b * 16;
        cp16(bd0, bh0 + (size_t)(k0 + kb) * BW + seg_b * 4);
        cp16(bd1, bh0 + (size_t)(k0 + kb + 16) * BW + seg_b * 4);
        cp16(bd0 + (OFF_BL - OFF_BH), bl0 + (size_t)(k0 + kb) * BW + seg_b * 4);
        cp16(bd1 + (OFF_BL - OFF_BH), bl0 + (size_t)(k0 + kb + 16) * BW + seg_b * 4);
    };
    auto compute = [&](int buf) {
        uint32_t st = sb + SM_STAGE + buf * STAGE_SZ;
#pragma unroll
        for (int sh = 0; sh < 2; sh++) {
            uint32_t ah[2][4], al[2][4], bh[8][2];
#pragma unroll
            for (int mt = 0; mt < 2; mt++) {
                uint32_t ao = st + OFF_AH + a_base + mt * 16 * ASTRIDE + sh * 32;
                ldsm4(ah[mt], ao);
                ldsm4(al[mt], ao + (OFF_AL - OFF_AH));
            }
#pragma unroll
            for (int jp = 0; jp < 4; jp++) {
                uint32_t r[4];
                ldsm4t(r, st + OFF_BH + b_base + sh * 16 * BSTRIDE + jp * 32);
                bh[2 * jp][0] = r[0]; bh[2 * jp][1] = r[1];
                bh[2 * jp + 1][0] = r[2]; bh[2 * jp + 1][1] = r[3];
            }
#pragma unroll
            for (int mt = 0; mt < 2; mt++)
#pragma unroll
                for (int j = 0; j < 8; j++) mma16816(c[mt][j], ah[mt], bh[j]);
#pragma unroll
            for (int mt = 0; mt < 2; mt++)
#pragma unroll
                for (int j = 0; j < 8; j++) mma16816(c[mt][j], al[mt], bh[j]);
#pragma unroll
            for (int jp = 0; jp < 4; jp++) {
                uint32_t r[4];
                ldsm4t(r, st + OFF_BL + b_base + sh * 16 * BSTRIDE + jp * 32);
#pragma unroll
                for (int mt = 0; mt < 2; mt++) {
                    mma16816(c[mt][2 * jp], ah[mt], r);
                    mma16816(c[mt][2 * jp + 1], ah[mt], r + 2);
                }
            }
        }
    };

    issue(0, 0); CP_COMMIT();
    issue(KC, 1); CP_COMMIT();
    int bufc = 0, bufi = 2;
#pragma unroll 1
    for (int ch = 0; ch < NCHUNK; ch++) {
        CP_WAIT1();
        __syncthreads();
        if (ch + 2 < NCHUNK) issue((ch + 2) * KC, bufi);
        CP_COMMIT();
        compute(bufc);
        bufc = (bufc + 1 == NSTAGE) ? 0 : bufc + 1;
        bufi = (bufi + 1 == NSTAGE) ? 0 : bufi + 1;
    }
}

// ---------------------------------------------------------------------------
__global__ void __launch_bounds__(256, 2)
ffn1_mma() {
    const int e = blockIdx.z;
    const int ne = g_count[e];
    const int row0 = blockIdx.x * 128;
    if (row0 >= ne) return;
    const int cbase = blockIdx.y * 64;

    extern __shared__ char smem[];
    uint32_t sb = smem_u32(smem);
    const int tid = threadIdx.x;
    if (tid < 128) {
        int r = row0 + tid;
        int tok = (r < ne) ? g_tok[e * MAXPE + r] : 0;   // dummy tok 0 for invalid rows
        ((int*)(smem + SM_TOK))[tid] = tok;
    }
    __syncthreads();
    const int r0 = tid >> 2;
    const int t0 = ((const int*)(smem + SM_TOK))[r0];
    const int t1 = ((const int*)(smem + SM_TOK))[r0 + 64];
    const uint32_t* a0h = g_xh + (size_t)t0 * (HD / 2);
    const uint32_t* a0l = g_xl + (size_t)t0 * (HD / 2);
    const uint32_t* a1h = g_xh + (size_t)t1 * (HD / 2);
    const uint32_t* a1l = g_xl + (size_t)t1 * (HD / 2);
    const uint32_t* bh0 = g_w13h + (size_t)e * HD * ID + cbase;
    const uint32_t* bl0 = g_w13l + (size_t)e * HD * ID + cbase;

    float c[2][8][4];
#pragma unroll
    for (int i = 0; i < 2; i++)
#pragma unroll
        for (int j = 0; j < 8; j++)
#pragma unroll
            for (int k = 0; k < 4; k++) c[i][j][k] = 0.f;

    gemm_pk<HD / KC, HD / 2, ID>(a0h, a0l, a1h, a1l, bh0, bl0, sb, c);

    // epilogue: silu(g)*u, pack adjacent col pairs via shfl, store hi/lo planes
    const int lane = tid & 31, w = tid >> 5, wm = w & 3, wn = w >> 2;
    const int g = lane >> 2, t = lane & 3;
#pragma unroll
    for (int mt = 0; mt < 2; mt++)
#pragma unroll
        for (int rr = 0; rr < 2; rr++) {
            int slot = row0 + wm * 32 + mt * 16 + rr * 8 + g;
            uint32_t* dh = g_acth + (size_t)(e * MAXPE + slot) * (ID / 2) + (cbase + wn * 32) / 2;
            uint32_t* dl = g_actl + (size_t)(e * MAXPE + slot) * (ID / 2) + (cbase + wn * 32) / 2;
#pragma unroll
            for (int j = 0; j < 8; j++) {
                float gg = c[mt][j][2 * rr], uu = c[mt][j][2 * rr + 1];
                float v = gg / (1.f + __expf(-gg)) * uu;
                float pv = __shfl_xor_sync(0xffffffffu, v, 1);
                if ((t & 1) == 0 && slot < ne) {
                    uint32_t hi, lo;
                    cvt_hl(v, pv, hi, lo);
                    int wi = 2 * j + (t >> 1);
                    dh[wi] = hi; dl[wi] = lo;
                }
            }
        }
}

// ---------------------------------------------------------------------------
__global__ void __launch_bounds__(256, 2)
ffn2_mma(float* __restrict__ out) {
    const int e = blockIdx.z;
    const int ne = g_count[e];
    const int row0 = blockIdx.x * 128;
    if (row0 >= ne) return;
    const int c0 = blockIdx.y * 128;

    extern __shared__ char smem[];
    uint32_t sb = smem_u32(smem);
    const int tid = threadIdx.x;
    if (tid < 128) {
        int r = row0 + tid;
        ((int*)(smem + SM_TOK))[tid]  = (r < ne) ? g_tok[e * MAXPE + r] : -1;
        ((float*)(smem + SM_WT))[tid] = (r < ne) ? g_wt[e * MAXPE + r] : 0.f;
    }
    __syncthreads();
    const int r0 = tid >> 2;
    const uint32_t* a0h = g_acth + (size_t)(e * MAXPE + row0 + r0) * (ID / 2);
    const uint32_t* a0l = g_actl + (size_t)(e * MAXPE + row0 + r0) * (ID / 2);
    const uint32_t* a1h = g_acth + (size_t)(e * MAXPE + row0 + r0 + 64) * (ID / 2);
    const uint32_t* a1l = g_actl + (size_t)(e * MAXPE + row0 + r0 + 64) * (ID / 2);
    const uint32_t* bh0 = g_w2h + (size_t)e * ID * (HD / 2) + c0 / 2;
    const uint32_t* bl0 = g_w2l + (size_t)e * ID * (HD / 2) + c0 / 2;

    float c[2][8][4];
#pragma unroll
    for (int i = 0; i < 2; i++)
#pragma unroll
        for (int j = 0; j < 8; j++)
#pragma unroll
            for (int k = 0; k < 4; k++) c[i][j][k] = 0.f;

    gemm_pk<ID / KC, ID / 2, HD / 2>(a0h, a0l, a1h, a1l, bh0, bl0, sb, c);

    const int lane = tid & 31, w = tid >> 5, wm = w & 3, wn = w >> 2;
    const int g = lane >> 2, t = lane & 3;
#pragma unroll
    for (int mt = 0; mt < 2; mt++)
#pragma unroll
        for (int rr = 0; rr < 2; rr++) {
            int rlocal = wm * 32 + mt * 16 + rr * 8 + g;
            int tok = ((const int*)(smem + SM_TOK))[rlocal];
            if (tok >= 0) {
                float wt = ((const float*)(smem + SM_WT))[rlocal];
                float* orow = out + (size_t)tok * HD + c0 + wn * 64;
#pragma unroll
                for (int j = 0; j < 8; j++)
                    red2(&orow[j * 8 + 2 * t],
                         wt * c[mt][j][2 * rr], wt * c[mt][j][2 * rr + 1]);
            }
        }
}

// ---------------------------------------------------------------------------
extern "C" void kernel_launch(void* const* d_in, const int* in_sizes, int n_in,
                              void* d_out, int out_size) {
    const float* x   = (const float*)d_in[0];
    const float* gw  = (const float*)d_in[1];
    const float* w13 = (const float*)d_in[2];
    const float* w2  = (const float*)d_in[3];
    float* out = (float*)d_out;

    cudaFuncSetAttribute(prep_kernel, cudaFuncAttributeMaxDynamicSharedMemorySize, PREP_SMEM);
    cudaFuncSetAttribute(ffn1_mma, cudaFuncAttributeMaxDynamicSharedMemorySize, SMEM_SZ);
    cudaFuncSetAttribute(ffn2_mma, cudaFuncAttributeMaxDynamicSharedMemorySize, SMEM_SZ);

    prep_kernel<<<PREP_TOT, 256, PREP_SMEM>>>(w13, w2, gw, x, (float4*)out);
    dim3 g1(MAXPE / 128, ID / 64, NE);    // (16, 16, 8)
    ffn1_mma<<<g1, 256, SMEM_SZ>>>();
    dim3 g2(MAXPE / 128, HD / 128, NE);   // (16, 16, 8)
    ffn2_mma<<<g2, 256, SMEM_SZ>>>(out);
    reset_kernel<<<1, 32>>>();
}

// round 17
// speedup vs baseline: 1.0142x; 1.0142x over previous
#include <cuda_runtime.h>
#include <cstdint>
#include <math.h>

#define NTOK 2048
#define HD   2048
#define NE   8
#define ID   1024
#define MAXPE 2048
#define KC   32
#define NSTAGE 3

__device__ int   g_count[NE];
__device__ int   g_tok[NE * MAXPE];
__device__ float g_wt [NE * MAXPE];
__device__ float g_gwT[NE * HD];                         // transposed gate weights
// packed bf16 hi/lo planes (word = bf16x2: lo16 = even element, hi16 = odd)
__device__ uint32_t g_w13h[(size_t)NE * HD * ID];        // word(e,k,n) = (gate_n, up_n)
__device__ uint32_t g_w13l[(size_t)NE * HD * ID];
__device__ uint32_t g_w2h [(size_t)NE * ID * (HD / 2)];  // word(e,k,j) = (w2[k,2j], w2[k,2j+1])
__device__ uint32_t g_w2l [(size_t)NE * ID * (HD / 2)];
__device__ uint32_t g_xh  [(size_t)NTOK * (HD / 2)];
__device__ uint32_t g_xl  [(size_t)NTOK * (HD / 2)];
__device__ uint32_t g_acth[(size_t)NE * MAXPE * (ID / 2)];
__device__ uint32_t g_actl[(size_t)NE * MAXPE * (ID / 2)];

// ---------------- helpers ----------------
__device__ __forceinline__ uint32_t smem_u32(const void* p) {
    uint32_t a;
    asm("{ .reg .u64 t; cvta.to.shared.u64 t, %1; cvt.u32.u64 %0, t; }" : "=r"(a) : "l"(p));
    return a;
}
__device__ __forceinline__ void cp16(uint32_t dst, const void* src) {
    asm volatile("cp.async.cg.shared.global [%0], [%1], 16;" :: "r"(dst), "l"(src) : "memory");
}
#define CP_COMMIT() asm volatile("cp.async.commit_group;" ::: "memory")
#define CP_WAIT1()  asm volatile("cp.async.wait_group 1;" ::: "memory")

__device__ __forceinline__ void cvt_hl(float a0, float a1, uint32_t& hi, uint32_t& lo) {
    uint32_t h;
    asm("cvt.rn.bf16x2.f32 %0, %1, %2;" : "=r"(h) : "f"(a1), "f"(a0));  // lo16=a0, hi16=a1
    float h0 = __uint_as_float(h << 16);
    float h1 = __uint_as_float(h & 0xFFFF0000u);
    uint32_t l;
    float l1 = a1 - h1, l0 = a0 - h0;
    asm("cvt.rn.bf16x2.f32 %0, %1, %2;" : "=r"(l) : "f"(l1), "f"(l0));
    hi = h; lo = l;
}
__device__ __forceinline__ void mma16816(float* c, const uint32_t* a, const uint32_t* b) {
    asm volatile("mma.sync.aligned.m16n8k16.row.col.f32.bf16.bf16.f32 "
        "{%0,%1,%2,%3}, {%4,%5,%6,%7}, {%8,%9}, {%0,%1,%2,%3};"
        : "+f"(c[0]), "+f"(c[1]), "+f"(c[2]), "+f"(c[3])
        : "r"(a[0]), "r"(a[1]), "r"(a[2]), "r"(a[3]), "r"(b[0]), "r"(b[1]));
}
__device__ __forceinline__ void ldsm4(uint32_t* r, uint32_t addr) {
    asm volatile("ldmatrix.sync.aligned.m8n8.x4.shared.b16 {%0,%1,%2,%3}, [%4];"
        : "=r"(r[0]), "=r"(r[1]), "=r"(r[2]), "=r"(r[3]) : "r"(addr));
}
__device__ __forceinline__ void ldsm4t(uint32_t* r, uint32_t addr) {
    asm volatile("ldmatrix.sync.aligned.m8n8.x4.trans.shared.b16 {%0,%1,%2,%3}, [%4];"
        : "=r"(r[0]), "=r"(r[1]), "=r"(r[2]), "=r"(r[3]) : "r"(addr));
}
// vector reduction: two adjacent f32 adds in one op (sm_90+)
__device__ __forceinline__ void red2(float* p, float a, float b) {
    asm volatile("red.global.add.v2.f32 [%0], {%1, %2};" :: "l"(p), "f"(a), "f"(b) : "memory");
}

// SMEM stage layout (identical geometry to validated R5/R8/R9/R11 kernels)
#define ASTRIDE 80
#define BSTRIDE 272
#define SZ_A (128 * ASTRIDE)
#define SZ_B (32 * BSTRIDE)
#define OFF_AH 0
#define OFF_AL SZ_A
#define OFF_BH (2 * SZ_A)
#define OFF_BL (2 * SZ_A + SZ_B)
#define STAGE_SZ (2 * SZ_A + 2 * SZ_B)     // 37888
#define SM_TOK 0
#define SM_WT  512
#define SM_STAGE 1024
#define SMEM_SZ (SM_STAGE + NSTAGE * STAGE_SZ)   // 114688 -> 2 CTAs/SM

// ---------------------------------------------------------------------------
// Fused prologue: pack13 | pack2 | init(out + counters) | packgw, one launch.
// Block ranges: [0,16384) pack13, [16384,24576) pack2, [24576,28672) init,
// [28672,28680) packgw. All four are mutually independent.
// ---------------------------------------------------------------------------
#define PREP_P13 16384
#define PREP_P2  (PREP_P13 + 8192)
#define PREP_INI (PREP_P2 + 4096)
#define PREP_GW  (PREP_INI + 8)

__global__ void prep_kernel(const float* __restrict__ w13,
                            const float* __restrict__ w2,
                            const float* __restrict__ gw,
                            float4* __restrict__ out4) {
    const int b = blockIdx.x, tid = threadIdx.x;
    if (b < PREP_P13) {
        size_t q = (size_t)b * 256 + tid;            // over NE*HD*ID/4
        size_t row = q / (ID / 4);
        int n = (int)(q % (ID / 4)) * 4;
        const float* base = w13 + row * (2 * ID);
        float4 gv = *(const float4*)(base + n);
        float4 uv = *(const float4*)(base + ID + n);
        uint4 h4, l4;
        cvt_hl(gv.x, uv.x, h4.x, l4.x);
        cvt_hl(gv.y, uv.y, h4.y, l4.y);
        cvt_hl(gv.z, uv.z, h4.z, l4.z);
        cvt_hl(gv.w, uv.w, h4.w, l4.w);
        size_t widx = row * ID + n;
        *(uint4*)&g_w13h[widx] = h4;
        *(uint4*)&g_w13l[widx] = l4;
    } else if (b < PREP_P2) {
        size_t q = (size_t)(b - PREP_P13) * 256 + tid;   // over NE*ID*HD/8
        const float4* src = (const float4*)w2 + q * 2;
        float4 v0 = src[0], v1 = src[1];
        uint4 h4, l4;
        cvt_hl(v0.x, v0.y, h4.x, l4.x);
        cvt_hl(v0.z, v0.w, h4.y, l4.y);
        cvt_hl(v1.x, v1.y, h4.z, l4.z);
        cvt_hl(v1.z, v1.w, h4.w, l4.w);
        *(uint4*)&g_w2h[q * 4] = h4;
        *(uint4*)&g_w2l[q * 4] = l4;
    } else if (b < PREP_INI) {
        int idx = (b - PREP_P2) * 256 + tid;             // over NTOK*HD/4
        if (b == PREP_P2 && tid < NE) g_count[tid] = 0;
        out4[idx] = make_float4(0.f, 0.f, 0.f, 0.f);
    } else {
        int h = (b - PREP_INI) * 256 + tid;              // over HD
        float4 g0 = *(const float4*)(gw + (size_t)h * NE);
        float4 g1 = *(const float4*)(gw + (size_t)h * NE + 4);
        g_gwT[0 * HD + h] = g0.x; g_gwT[1 * HD + h] = g0.y;
        g_gwT[2 * HD + h] = g0.z; g_gwT[3 * HD + h] = g0.w;
        g_gwT[4 * HD + h] = g1.x; g_gwT[5 * HD + h] = g1.y;
        g_gwT[6 * HD + h] = g1.z; g_gwT[7 * HD + h] = g1.w;
    }
}

// ---------------------------------------------------------------------------
// Router (fused x packing), 2 tokens per block: each g_gwT load feeds both
// tokens' fmaf chains (halves gwT requests + per-block fixed cost). Per-token
// accumulation order identical to the validated 1-token version.
// ---------------------------------------------------------------------------
__global__ void router_kernel(const float* __restrict__ x) {
    const int tid = threadIdx.x;
    const int t0 = blockIdx.x * 2, t1 = t0 + 1;
    float p0[NE], p1[NE];
#pragma unroll
    for (int e = 0; e < NE; e++) { p0[e] = 0.f; p1[e] = 0.f; }
    const float* xr0 = x + (size_t)t0 * HD;
    const float* xr1 = x + (size_t)t1 * HD;
#pragma unroll
    for (int blk = 0; blk < 2; blk++) {
        int h0 = blk * 1024 + tid * 4;
        float4 xv0 = *(const float4*)(xr0 + h0);
        float4 xv1 = *(const float4*)(xr1 + h0);
        uint4 h4, l4_;
        cvt_hl(xv0.x, xv0.y, h4.x, l4_.x);
        cvt_hl(xv0.z, xv0.w, h4.y, l4_.y);
        cvt_hl(xv1.x, xv1.y, h4.z, l4_.z);
        cvt_hl(xv1.z, xv1.w, h4.w, l4_.w);
        size_t wb0 = (size_t)t0 * (HD / 2) + h0 / 2;
        size_t wb1 = (size_t)t1 * (HD / 2) + h0 / 2;
        *(uint2*)&g_xh[wb0] = make_uint2(h4.x, h4.y);
        *(uint2*)&g_xl[wb0] = make_uint2(l4_.x, l4_.y);
        *(uint2*)&g_xh[wb1] = make_uint2(h4.z, h4.w);
        *(uint2*)&g_xl[wb1] = make_uint2(l4_.z, l4_.w);
#pragma unroll
        for (int e = 0; e < NE; e++) {
            float4 gv = *(const float4*)(g_gwT + (size_t)e * HD + h0);
            p0[e] = fmaf(xv0.x, gv.x, p0[e]);
            p0[e] = fmaf(xv0.y, gv.y, p0[e]);
            p0[e] = fmaf(xv0.z, gv.z, p0[e]);
            p0[e] = fmaf(xv0.w, gv.w, p0[e]);
            p1[e] = fmaf(xv1.x, gv.x, p1[e]);
            p1[e] = fmaf(xv1.y, gv.y, p1[e]);
            p1[e] = fmaf(xv1.z, gv.z, p1[e]);
            p1[e] = fmaf(xv1.w, gv.w, p1[e]);
        }
    }
#pragma unroll
    for (int e = 0; e < NE; e++) {
#pragma unroll
        for (int o = 16; o > 0; o >>= 1) {
            p0[e] += __shfl_xor_sync(0xffffffffu, p0[e], o);
            p1[e] += __shfl_xor_sync(0xffffffffu, p1[e], o);
        }
    }
    __shared__ float s[8][2 * NE];
    int warp = tid >> 5, lane = tid & 31;
    if (lane == 0) {
#pragma unroll
        for (int e = 0; e < NE; e++) { s[warp][e] = p0[e]; s[warp][NE + e] = p1[e]; }
    }
    __syncthreads();
    if (tid == 0) {
#pragma unroll
        for (int tk = 0; tk < 2; tk++) {
            float logit[NE];
#pragma unroll
            for (int e = 0; e < NE; e++) {
                float v = 0.f;
#pragma unroll
                for (int w = 0; w < 8; w++) v += s[w][tk * NE + e];
                logit[e] = v;
            }
            int i0 = 0;
#pragma unroll
            for (int e = 1; e < NE; e++) if (logit[e] > logit[i0]) i0 = e;
            int i1 = -1;
#pragma unroll
            for (int e = 0; e < NE; e++)
                if (e != i0 && (i1 < 0 || logit[e] > logit[i1])) i1 = e;
            float pr = expf(logit[i1] - logit[i0]);
            int t = t0 + tk;
            int q0 = atomicAdd(&g_count[i0], 1);
            g_tok[i0 * MAXPE + q0] = t; g_wt[i0 * MAXPE + q0] = 1.f / (1.f + pr);
            int q1 = atomicAdd(&g_count[i1], 1);
            g_tok[i1 * MAXPE + q1] = t; g_wt[i1 * MAXPE + q1] = pr / (1.f + pr);
        }
    }
}

// ---------------------------------------------------------------------------
// GEMM (R11 exact): 256 threads, 8 warps as 4M x 2N, CTA 128x128, pure
// cp.async from packed planes, 3-stage ring. bf16x3 (ah*bh, al*bh, ah*bl),
// bl loaded per-jp in pass 3 (register-pressure-optimal schedule).
// ---------------------------------------------------------------------------
template <int NCHUNK, int AW, int BW>
__device__ __forceinline__ void gemm_pk(
    const uint32_t* __restrict__ a0h, const uint32_t* __restrict__ a0l,  // row r0 = tid>>2
    const uint32_t* __restrict__ a1h, const uint32_t* __restrict__ a1l,  // row r0+64
    const uint32_t* __restrict__ bh0, const uint32_t* __restrict__ bl0,
    uint32_t sb, float c[2][8][4])
{
    const int tid = threadIdx.x;
    const int lane = tid & 31, w = tid >> 5;
    const int wm = w & 3, wn = w >> 2;
    const int lrow8 = ((lane >> 3) & 1) * 8 + (lane & 7);
    const int lk16 = (lane & 16) ? 16 : 0;
    const uint32_t a_base = (uint32_t)(wm * 32 + lrow8) * ASTRIDE + lk16;
    const uint32_t b_base = (uint32_t)lrow8 * BSTRIDE + wn * 128 + lk16;
    const int r0 = tid >> 2, seg_a = tid & 3;
    const int kb = tid >> 4, seg_b = tid & 15;

    auto issue = [&](int k0, int buf) {
        uint32_t st = sb + SM_STAGE + buf * STAGE_SZ;
        const int kw = k0 / 2;
        uint32_t ad0 = st + OFF_AH + r0 * ASTRIDE + seg_a * 16;
        uint32_t ad1 = st + OFF_AH + (r0 + 64) * ASTRIDE + seg_a * 16;
        cp16(ad0, a0h + kw + seg_a * 4);
        cp16(ad1, a1h + kw + seg_a * 4);
        cp16(ad0 + (OFF_AL - OFF_AH), a0l + kw + seg_a * 4);
        cp16(ad1 + (OFF_AL - OFF_AH), a1l + kw + seg_a * 4);
        uint32_t bd0 = st + OFF_BH + kb * BSTRIDE + seg_b * 16;
        uint32_t bd1 = st + OFF_BH + (kb + 16) * BSTRIDE + seg_b * 16;
        cp16(bd0, bh0 + (size_t)(k0 + kb) * BW + seg_b * 4);
        cp16(bd1, bh0 + (size_t)(k0 + kb + 16) * BW + seg_b * 4);
        cp16(bd0 + (OFF_BL - OFF_BH), bl0 + (size_t)(k0 + kb) * BW + seg_b * 4);
        cp16(bd1 + (OFF_BL - OFF_BH), bl0 + (size_t)(k0 + kb + 16) * BW + seg_b * 4);
    };
    auto compute = [&](int buf) {
        uint32_t st = sb + SM_STAGE + buf * STAGE_SZ;
#pragma unroll
        for (int sh = 0; sh < 2; sh++) {
            uint32_t ah[2][4], al[2][4], bh[8][2];
#pragma unroll
            for (int mt = 0; mt < 2; mt++) {
                uint32_t ao = st + OFF_AH + a_base + mt * 16 * ASTRIDE + sh * 32;
                ldsm4(ah[mt], ao);
                ldsm4(al[mt], ao + (OFF_AL - OFF_AH));
            }
#pragma unroll
            for (int jp = 0; jp < 4; jp++) {
                uint32_t r[4];
                ldsm4t(r, st + OFF_BH + b_base + sh * 16 * BSTRIDE + jp * 32);
                bh[2 * jp][0] = r[0]; bh[2 * jp][1] = r[1];
                bh[2 * jp + 1][0] = r[2]; bh[2 * jp + 1][1] = r[3];
            }
#pragma unroll
            for (int mt = 0; mt < 2; mt++)
#pragma unroll
                for (int j = 0; j < 8; j++) mma16816(c[mt][j], ah[mt], bh[j]);
#pragma unroll
            for (int mt = 0; mt < 2; mt++)
#pragma unroll
                for (int j = 0; j < 8; j++) mma16816(c[mt][j], al[mt], bh[j]);
#pragma unroll
            for (int jp = 0; jp < 4; jp++) {
                uint32_t r[4];
                ldsm4t(r, st + OFF_BL + b_base + sh * 16 * BSTRIDE + jp * 32);
#pragma unroll
                for (int mt = 0; mt < 2; mt++) {
                    mma16816(c[mt][2 * jp], ah[mt], r);
                    mma16816(c[mt][2 * jp + 1], ah[mt], r + 2);
                }
            }
        }
    };

    issue(0, 0); CP_COMMIT();
    issue(KC, 1); CP_COMMIT();
    int bufc = 0, bufi = 2;
#pragma unroll 1
    for (int ch = 0; ch < NCHUNK; ch++) {
        CP_WAIT1();
        __syncthreads();
        if (ch + 2 < NCHUNK) issue((ch + 2) * KC, bufi);
        CP_COMMIT();
        compute(bufc);
        bufc = (bufc + 1 == NSTAGE) ? 0 : bufc + 1;
        bufi = (bufi + 1 == NSTAGE) ? 0 : bufi + 1;
    }
}

// ---------------------------------------------------------------------------
__global__ void __launch_bounds__(256, 2)
ffn1_mma() {
    const int e = blockIdx.z;
    const int ne = g_count[e];
    const int row0 = blockIdx.x * 128;
    if (row0 >= ne) return;
    const int cbase = blockIdx.y * 64;

    extern __shared__ char smem[];
    uint32_t sb = smem_u32(smem);
    const int tid = threadIdx.x;
    if (tid < 128) {
        int r = row0 + tid;
        int tok = (r < ne) ? g_tok[e * MAXPE + r] : 0;   // dummy tok 0 for invalid rows
        ((int*)(smem + SM_TOK))[tid] = tok;
    }
    __syncthreads();
    const int r0 = tid >> 2;
    const int t0 = ((const int*)(smem + SM_TOK))[r0];
    const int t1 = ((const int*)(smem + SM_TOK))[r0 + 64];
    const uint32_t* a0h = g_xh + (size_t)t0 * (HD / 2);
    const uint32_t* a0l = g_xl + (size_t)t0 * (HD / 2);
    const uint32_t* a1h = g_xh + (size_t)t1 * (HD / 2);
    const uint32_t* a1l = g_xl + (size_t)t1 * (HD / 2);
    const uint32_t* bh0 = g_w13h + (size_t)e * HD * ID + cbase;
    const uint32_t* bl0 = g_w13l + (size_t)e * HD * ID + cbase;

    float c[2][8][4];
#pragma unroll
    for (int i = 0; i < 2; i++)
#pragma unroll
        for (int j = 0; j < 8; j++)
#pragma unroll
            for (int k = 0; k < 4; k++) c[i][j][k] = 0.f;

    gemm_pk<HD / KC, HD / 2, ID>(a0h, a0l, a1h, a1l, bh0, bl0, sb, c);

    // epilogue: silu(g)*u, pack adjacent col pairs via shfl, store hi/lo planes
    const int lane = tid & 31, w = tid >> 5, wm = w & 3, wn = w >> 2;
    const int g = lane >> 2, t = lane & 3;
#pragma unroll
    for (int mt = 0; mt < 2; mt++)
#pragma unroll
        for (int rr = 0; rr < 2; rr++) {
            int slot = row0 + wm * 32 + mt * 16 + rr * 8 + g;
            uint32_t* dh = g_acth + (size_t)(e * MAXPE + slot) * (ID / 2) + (cbase + wn * 32) / 2;
            uint32_t* dl = g_actl + (size_t)(e * MAXPE + slot) * (ID / 2) + (cbase + wn * 32) / 2;
#pragma unroll
            for (int j = 0; j < 8; j++) {
                float gg = c[mt][j][2 * rr], uu = c[mt][j][2 * rr + 1];
                float v = gg / (1.f + __expf(-gg)) * uu;
                float pv = __shfl_xor_sync(0xffffffffu, v, 1);
                if ((t & 1) == 0 && slot < ne) {
                    uint32_t hi, lo;
                    cvt_hl(v, pv, hi, lo);
                    int wi = 2 * j + (t >> 1);
                    dh[wi] = hi; dl[wi] = lo;
                }
            }
        }
}

// ---------------------------------------------------------------------------
__global__ void __launch_bounds__(256, 2)
ffn2_mma(float* __restrict__ out) {
    const int e = blockIdx.z;
    const int ne = g_count[e];
    const int row0 = blockIdx.x * 128;
    if (row0 >= ne) return;
    const int c0 = blockIdx.y * 128;

    extern __shared__ char smem[];
    uint32_t sb = smem_u32(smem);
    const int tid = threadIdx.x;
    if (tid < 128) {
        int r = row0 + tid;
        ((int*)(smem + SM_TOK))[tid]  = (r < ne) ? g_tok[e * MAXPE + r] : -1;
        ((float*)(smem + SM_WT))[tid] = (r < ne) ? g_wt[e * MAXPE + r] : 0.f;
    }
    __syncthreads();
    const int r0 = tid >> 2;
    const uint32_t* a0h = g_acth + (size_t)(e * MAXPE + row0 + r0) * (ID / 2);
    const uint32_t* a0l = g_actl + (size_t)(e * MAXPE + row0 + r0) * (ID / 2);
    const uint32_t* a1h = g_acth + (size_t)(e * MAXPE + row0 + r0 + 64) * (ID / 2);
    const uint32_t* a1l = g_actl + (size_t)(e * MAXPE + row0 + r0 + 64) * (ID / 2);
    const uint32_t* bh0 = g_w2h + (size_t)e * ID * (HD / 2) + c0 / 2;
    const uint32_t* bl0 = g_w2l + (size_t)e * ID * (HD / 2) + c0 / 2;

    float c[2][8][4];
#pragma unroll
    for (int i = 0; i < 2; i++)
#pragma unroll
        for (int j = 0; j < 8; j++)
#pragma unroll
            for (int k = 0; k < 4; k++) c[i][j][k] = 0.f;

    gemm_pk<ID / KC, ID / 2, HD / 2>(a0h, a0l, a1h, a1l, bh0, bl0, sb, c);

    const int lane = tid & 31, w = tid >> 5, wm = w & 3, wn = w >> 2;
    const int g = lane >> 2, t = lane & 3;
#pragma unroll
    for (int mt = 0; mt < 2; mt++)
#pragma unroll
        for (int rr = 0; rr < 2; rr++) {
            int rlocal = wm * 32 + mt * 16 + rr * 8 + g;
            int tok = ((const int*)(smem + SM_TOK))[rlocal];
            if (tok >= 0) {
                float wt = ((const float*)(smem + SM_WT))[rlocal];
                float* orow = out + (size_t)tok * HD + c0 + wn * 64;
#pragma unroll
                for (int j = 0; j < 8; j++)
                    red2(&orow[j * 8 + 2 * t],
                         wt * c[mt][j][2 * rr], wt * c[mt][j][2 * rr + 1]);
            }
        }
}

// ---------------------------------------------------------------------------
extern "C" void kernel_launch(void* const* d_in, const int* in_sizes, int n_in,
                              void* d_out, int out_size) {
    const float* x   = (const float*)d_in[0];
    const float* gw  = (const float*)d_in[1];
    const float* w13 = (const float*)d_in[2];
    const float* w2  = (const float*)d_in[3];
    float* out = (float*)d_out;

    cudaFuncSetAttribute(ffn1_mma, cudaFuncAttributeMaxDynamicSharedMemorySize, SMEM_SZ);
    cudaFuncSetAttribute(ffn2_mma, cudaFuncAttributeMaxDynamicSharedMemorySize, SMEM_SZ);

    prep_kernel<<<PREP_GW, 256>>>(w13, w2, gw, (float4*)out);
    router_kernel<<<NTOK / 2, 256>>>(x);
    dim3 g1(MAXPE / 128, ID / 64, NE);    // (16, 16, 8)
    ffn1_mma<<<g1, 256, SMEM_SZ>>>();
    dim3 g2(MAXPE / 128, HD / 128, NE);   // (16, 16, 8)
    ffn2_mma<<<g2, 256, SMEM_SZ>>>(out);
}